// round 9
// baseline (speedup 1.0000x reference)
#include <cuda_runtime.h>
#include <cstdint>

// Fixed dataset shape: B=4, n=4096/batch, C=20, NSAMPLE=32, R=2, cube 20.
#define NS      32
#define CCH     20
#define SPLITS  32           // mask layout: 32 uint4 per query (4096 bits)
#define TPB2    256          // group: 8 warps -> 8 queries per block
#define MAXM    16384
#define NBATCH  4
#define GD      8            // grid cells per dim (cell size 2.5)
#define CELLS   512          // 8^3 per batch
#define FULL    0xFFFFFFFFu

// Scratch (device globals: allocation-free rule).
__device__ unsigned g_mask[(size_t)MAXM * 128];      // 4096-bit hit mask per query (8 MB)
__device__ int      g_labels[MAXM];
__device__ int      g_cellcnt[NBATCH * CELLS];
__device__ int      g_cellstart[NBATCH * CELLS];
__device__ int      g_cursor[NBATCH * CELLS];
__device__ float4   g_pts[MAXM];                     // {x, y, z, local_idx_as_float}

__device__ __forceinline__ int cell_of(float v) {
    int c = (int)(v * 0.4f);                         // / 2.5
    c = c < 0 ? 0 : (c > GD - 1 ? GD - 1 : c);
    return c;
}

// ---------------------------------------------------------------------------
// Kernel A: bin count + one-hot label extraction (folded).
// ---------------------------------------------------------------------------
__global__ void __launch_bounds__(256)
bin_label_kernel(const float* __restrict__ xyz,
                 const float* __restrict__ tgt,
                 int n) {
    const int i = blockIdx.x * 256 + threadIdx.x;
    const int b = i / n;

    const float x = xyz[3 * (size_t)i + 0];
    const float y = xyz[3 * (size_t)i + 1];
    const float z = xyz[3 * (size_t)i + 2];
    const int cid = (cell_of(x) * GD + cell_of(y)) * GD + cell_of(z);
    atomicAdd(&g_cellcnt[b * CELLS + cid], 1);

    const float4* r4 = (const float4*)(tgt + (size_t)i * CCH);
    int lab = 0;
#pragma unroll
    for (int j = 0; j < 5; j++) {
        const float4 v = r4[j];
        if (v.x > 0.5f) lab = 4 * j + 0;
        if (v.y > 0.5f) lab = 4 * j + 1;
        if (v.z > 0.5f) lab = 4 * j + 2;
        if (v.w > 0.5f) lab = 4 * j + 3;
    }
    g_labels[i] = lab;
}

// ---------------------------------------------------------------------------
// Kernel B: exclusive prefix over the 2048 cell counts. One block.
// ---------------------------------------------------------------------------
__global__ void __launch_bounds__(1024)
scan_kernel() {
    __shared__ int s[1024];
    const int t = threadIdx.x;
    const int a = g_cellcnt[2 * t];
    const int b = g_cellcnt[2 * t + 1];
    s[t] = a + b;
    __syncthreads();
#pragma unroll
    for (int d = 1; d < 1024; d <<= 1) {
        const int v = (t >= d) ? s[t - d] : 0;
        __syncthreads();
        s[t] += v;
        __syncthreads();
    }
    const int e = (t > 0) ? s[t - 1] : 0;
    g_cellstart[2 * t]     = e;       g_cursor[2 * t]     = e;
    g_cellstart[2 * t + 1] = e + a;   g_cursor[2 * t + 1] = e + a;
}

// ---------------------------------------------------------------------------
// Kernel C: scatter points into cell-sorted order.
// ---------------------------------------------------------------------------
__global__ void __launch_bounds__(256)
scatter_kernel(const float* __restrict__ xyz, int n) {
    const int i = blockIdx.x * 256 + threadIdx.x;
    const int b = i / n;

    const float x = xyz[3 * (size_t)i + 0];
    const float y = xyz[3 * (size_t)i + 1];
    const float z = xyz[3 * (size_t)i + 2];
    const int cid = (cell_of(x) * GD + cell_of(y)) * GD + cell_of(z);
    const int slot = atomicAdd(&g_cursor[b * CELLS + cid], 1);
    g_pts[slot] = make_float4(x, y, z, __int_as_float(i - b * n));
}

// ---------------------------------------------------------------------------
// Kernel D: grid ball query. One thread per query; 3x3 (x,y) neighbor cells,
// each with a CONTIGUOUS z-run of points (cells consecutive in z => their
// scatter ranges are consecutive). Exact per-op-RN d2 test; hits -> atomicOr
// into the query's bitmask (bit order == index order, so first-32 semantics
// are preserved for free).
// ---------------------------------------------------------------------------
__global__ void __launch_bounds__(128)
grid_query_kernel(const float* __restrict__ new_xyz, int n, float r2) {
    const int q = blockIdx.x * 128 + threadIdx.x;
    const int b = q / n;

    const float qx = new_xyz[3 * (size_t)q + 0];
    const float qy = new_xyz[3 * (size_t)q + 1];
    const float qz = new_xyz[3 * (size_t)q + 2];

    const int cx = cell_of(qx), cy = cell_of(qy), cz = cell_of(qz);
    const int xlo = cx > 0 ? cx - 1 : 0, xhi = cx < GD - 1 ? cx + 1 : GD - 1;
    const int ylo = cy > 0 ? cy - 1 : 0, yhi = cy < GD - 1 ? cy + 1 : GD - 1;
    const int zlo = cz > 0 ? cz - 1 : 0, zhi = cz < GD - 1 ? cz + 1 : GD - 1;

    unsigned* mask = g_mask + (size_t)q * 128;

    for (int ix = xlo; ix <= xhi; ix++) {
        for (int iy = ylo; iy <= yhi; iy++) {
            const int cbase = b * CELLS + (ix * GD + iy) * GD;
            const int st = g_cellstart[cbase + zlo];
            const int en = g_cellstart[cbase + zhi] +
                           (g_cursor[cbase + zhi] - g_cellstart[cbase + zhi]);
            for (int k = st; k < en; k++) {
                const float4 p = g_pts[k];
                const float dx = __fadd_rn(p.x, -qx);
                const float dy = __fadd_rn(p.y, -qy);
                const float dz = __fadd_rn(p.z, -qz);
                const float d2 = __fadd_rn(__fadd_rn(__fmul_rn(dx, dx),
                                                     __fmul_rn(dy, dy)),
                                           __fmul_rn(dz, dz));
                if (d2 < r2) {
                    const int j = __float_as_int(p.w);
                    atomicOr(&mask[j >> 5], 1u << (j & 31));
                }
            }
        }
    }
}

// ---------------------------------------------------------------------------
// Kernel E: warp-per-query group (unchanged from R7/R8 WIN version).
// ---------------------------------------------------------------------------
__global__ void __launch_bounds__(TPB2)
group_kernel(const float* __restrict__ pred,
             float* __restrict__ out_pred,
             float* __restrict__ out_tgt,
             float* __restrict__ out_w,
             int n) {
    __shared__ int sidx[TPB2 / 32][NS];

    const int w    = threadIdx.x >> 5;
    const int lane = threadIdx.x & 31;
    const int i    = blockIdx.x * (TPB2 / 32) + w;

    const uint4 mv = ((const uint4*)g_mask)[(size_t)i * SPLITS + lane];
    const int myc = __popc(mv.x) + __popc(mv.y) + __popc(mv.z) + __popc(mv.w);

    int incl = myc;
#pragma unroll
    for (int d = 1; d < 32; d <<= 1) {
        int v = __shfl_up_sync(FULL, incl, d);
        if (lane >= d) incl += v;
    }
    int total = __shfl_sync(FULL, incl, 31);
    if (total > NS) total = NS;
    int pos = incl - myc;

    const int pbase = lane * 128;
    unsigned ww;
    ww = mv.x; while (ww) { int t = __ffs(ww) - 1; if (pos < NS) sidx[w][pos] = pbase + t;       pos++; ww &= ww - 1; }
    ww = mv.y; while (ww) { int t = __ffs(ww) - 1; if (pos < NS) sidx[w][pos] = pbase + 32 + t;  pos++; ww &= ww - 1; }
    ww = mv.z; while (ww) { int t = __ffs(ww) - 1; if (pos < NS) sidx[w][pos] = pbase + 64 + t;  pos++; ww &= ww - 1; }
    ww = mv.w; while (ww) { int t = __ffs(ww) - 1; if (pos < NS) sidx[w][pos] = pbase + 96 + t;  pos++; ww &= ww - 1; }
    __syncwarp();

    const int idx  = sidx[w][lane < total ? lane : 0];
    const int rowg = (i / n) * n + idx;

    {
        const float4* fr = (const float4*)(pred + (size_t)rowg * CCH);
        float4 rr[5];
#pragma unroll
        for (int j = 0; j < 5; j++) rr[j] = fr[j];
        const float* ff = (const float*)rr;

        const float cv = (lane < CCH) ? pred[(size_t)i * CCH + lane] : 0.0f;
        float* o = out_pred + (size_t)i * (CCH * NS);
#pragma unroll
        for (int c = 0; c < CCH; c++)
            o[c * NS + lane] = ff[c] - __shfl_sync(FULL, cv, c);
    }

    {
        const int labk = g_labels[rowg];
        const int labi = g_labels[i];
        float* o = out_tgt + (size_t)i * (CCH * NS);
#pragma unroll
        for (int c = 0; c < CCH; c++) {
            const float a = (labk == c) ? 1.0f : 0.0f;
            const float b = (labi == c) ? 1.0f : 0.0f;
            o[c * NS + lane] = a - b;
        }
    }

    out_w[(size_t)i * NS + lane] = (lane < total) ? (1.0f / (float)total) : 0.0f;
}

// ---------------------------------------------------------------------------
// Launch. Inputs: xyz, xyz_batch_cnt, pred, tgt, new_xyz, new_xyz_batch_cnt.
// Output: concat(pred_local (m,C,NS), tgt_local (m,C,NS), weight (m,NS)) f32.
// All ops are graph-capturable (kernels + memset nodes; no allocs).
// ---------------------------------------------------------------------------
extern "C" void kernel_launch(void* const* d_in, const int* in_sizes, int n_in,
                              void* d_out, int out_size) {
    const float* xyz     = (const float*)d_in[0];
    const float* pred    = (const float*)d_in[2];
    const float* tgt     = (const float*)d_in[3];
    const float* new_xyz = (const float*)d_in[4];

    const int nb = in_sizes[1];          // 4
    const int N  = in_sizes[0] / 3;      // 16384
    const int n  = N / nb;               // 4096
    const int m  = in_sizes[4] / 3;      // 16384

    float* out_pred = (float*)d_out;
    float* out_tgt  = out_pred + (size_t)m * CCH * NS;
    float* out_w    = out_tgt  + (size_t)m * CCH * NS;

    void* mask_ptr = nullptr;
    void* cnt_ptr  = nullptr;
    cudaGetSymbolAddress(&mask_ptr, g_mask);
    cudaGetSymbolAddress(&cnt_ptr,  g_cellcnt);
    cudaMemsetAsync(mask_ptr, 0, (size_t)MAXM * 128 * sizeof(unsigned));
    cudaMemsetAsync(cnt_ptr,  0, NBATCH * CELLS * sizeof(int));

    bin_label_kernel<<<N / 256, 256>>>(xyz, tgt, n);
    scan_kernel<<<1, 1024>>>();
    scatter_kernel<<<N / 256, 256>>>(xyz, n);
    grid_query_kernel<<<m / 128, 128>>>(new_xyz, n, 4.0f);
    group_kernel<<<m / (TPB2 / 32), TPB2>>>(pred, out_pred, out_tgt, out_w, n);
}

// round 12
// speedup vs baseline: 1.7917x; 1.7917x over previous
#include <cuda_runtime.h>
#include <cstdint>

// Fixed dataset shape: B=4, n=4096/batch, C=20, NSAMPLE=32, R=2, cube 20.
#define NS      32
#define CCH     20
#define SPLITS  32           // mask layout: 32 uint4 per query (4096 bits)
#define TPB2    256          // group: 8 warps -> 8 queries per block
#define MAXM    16384
#define NBATCH  4
#define GD      8            // grid cells per dim (cell size 2.5)
#define CELLS   512          // 8^3 per batch
#define FULL    0xFFFFFFFFu

// Scratch (device globals: allocation-free rule).
__device__ unsigned g_mask[(size_t)MAXM * 128];      // 4096-bit hit mask per query (8 MB)
__device__ int      g_labels[MAXM];
__device__ int      g_cellcnt[NBATCH * CELLS];
__device__ int      g_cellstart[NBATCH * CELLS];
__device__ int      g_cursor[NBATCH * CELLS];
__device__ float4   g_pts[MAXM];                     // {x, y, z, local_idx_as_float}

__device__ __forceinline__ int cell_of(float v) {
    int c = (int)(v * 0.4f);                         // / 2.5
    c = c < 0 ? 0 : (c > GD - 1 ? GD - 1 : c);
    return c;
}

// ---------------------------------------------------------------------------
// Kernel A: bin count + one-hot label extraction (folded).
// ---------------------------------------------------------------------------
__global__ void __launch_bounds__(256)
bin_label_kernel(const float* __restrict__ xyz,
                 const float* __restrict__ tgt,
                 int n) {
    const int i = blockIdx.x * 256 + threadIdx.x;
    const int b = i / n;

    const float x = xyz[3 * (size_t)i + 0];
    const float y = xyz[3 * (size_t)i + 1];
    const float z = xyz[3 * (size_t)i + 2];
    const int cid = (cell_of(x) * GD + cell_of(y)) * GD + cell_of(z);
    atomicAdd(&g_cellcnt[b * CELLS + cid], 1);

    const float4* r4 = (const float4*)(tgt + (size_t)i * CCH);
    int lab = 0;
#pragma unroll
    for (int j = 0; j < 5; j++) {
        const float4 v = r4[j];
        if (v.x > 0.5f) lab = 4 * j + 0;
        if (v.y > 0.5f) lab = 4 * j + 1;
        if (v.z > 0.5f) lab = 4 * j + 2;
        if (v.w > 0.5f) lab = 4 * j + 3;
    }
    g_labels[i] = lab;
}

// ---------------------------------------------------------------------------
// Kernel B: exclusive prefix over the 2048 cell counts. One block.
// ---------------------------------------------------------------------------
__global__ void __launch_bounds__(1024)
scan_kernel() {
    __shared__ int s[1024];
    const int t = threadIdx.x;
    const int a = g_cellcnt[2 * t];
    const int b = g_cellcnt[2 * t + 1];
    s[t] = a + b;
    __syncthreads();
#pragma unroll
    for (int d = 1; d < 1024; d <<= 1) {
        const int v = (t >= d) ? s[t - d] : 0;
        __syncthreads();
        s[t] += v;
        __syncthreads();
    }
    const int e = (t > 0) ? s[t - 1] : 0;
    g_cellstart[2 * t]     = e;       g_cursor[2 * t]     = e;
    g_cellstart[2 * t + 1] = e + a;   g_cursor[2 * t + 1] = e + a;
}

// ---------------------------------------------------------------------------
// Kernel C: scatter points into cell-sorted order.
// ---------------------------------------------------------------------------
__global__ void __launch_bounds__(256)
scatter_kernel(const float* __restrict__ xyz, int n) {
    const int i = blockIdx.x * 256 + threadIdx.x;
    const int b = i / n;

    const float x = xyz[3 * (size_t)i + 0];
    const float y = xyz[3 * (size_t)i + 1];
    const float z = xyz[3 * (size_t)i + 2];
    const int cid = (cell_of(x) * GD + cell_of(y)) * GD + cell_of(z);
    const int slot = atomicAdd(&g_cursor[b * CELLS + cid], 1);
    g_pts[slot] = make_float4(x, y, z, __int_as_float(i - b * n));
}

// ---------------------------------------------------------------------------
// Kernel D: grid ball query, WARP per query. For each of <=9 (x,y) neighbor
// columns, the z-range [zlo..zhi] is one contiguous run of sorted points;
// 32 lanes stride it with coalesced float4 loads (L2-resident). Exact
// per-op-RN d2 test; hits -> atomicOr into the query's bitmask (bit order ==
// index order => first-32 semantics preserved).
// ---------------------------------------------------------------------------
__global__ void __launch_bounds__(256)
grid_query_kernel(const float* __restrict__ new_xyz, int n, float r2) {
    const int w    = threadIdx.x >> 5;
    const int lane = threadIdx.x & 31;
    const int q    = blockIdx.x * 8 + w;
    const int b    = q / n;

    const float qx = new_xyz[3 * (size_t)q + 0];
    const float qy = new_xyz[3 * (size_t)q + 1];
    const float qz = new_xyz[3 * (size_t)q + 2];

    const int cx = cell_of(qx), cy = cell_of(qy), cz = cell_of(qz);
    const int xlo = cx > 0 ? cx - 1 : 0, xhi = cx < GD - 1 ? cx + 1 : GD - 1;
    const int ylo = cy > 0 ? cy - 1 : 0, yhi = cy < GD - 1 ? cy + 1 : GD - 1;
    const int zlo = cz > 0 ? cz - 1 : 0, zhi = cz < GD - 1 ? cz + 1 : GD - 1;

    unsigned* mask = g_mask + (size_t)q * 128;

    for (int ix = xlo; ix <= xhi; ix++) {
        for (int iy = ylo; iy <= yhi; iy++) {
            const int cbase = b * CELLS + (ix * GD + iy) * GD;
            const int st = g_cellstart[cbase + zlo];
            const int en = g_cursor[cbase + zhi];     // == start + count of zhi
            for (int k = st + lane; k < en; k += 32) {
                const float4 p = g_pts[k];
                const float dx = __fadd_rn(p.x, -qx);
                const float dy = __fadd_rn(p.y, -qy);
                const float dz = __fadd_rn(p.z, -qz);
                const float d2 = __fadd_rn(__fadd_rn(__fmul_rn(dx, dx),
                                                     __fmul_rn(dy, dy)),
                                           __fmul_rn(dz, dz));
                if (d2 < r2) {
                    const int j = __float_as_int(p.w);
                    atomicOr(&mask[j >> 5], 1u << (j & 31));
                }
            }
        }
    }
}

// ---------------------------------------------------------------------------
// Kernel E: warp-per-query group (R7 WIN version, unchanged).
// ---------------------------------------------------------------------------
__global__ void __launch_bounds__(TPB2)
group_kernel(const float* __restrict__ pred,
             float* __restrict__ out_pred,
             float* __restrict__ out_tgt,
             float* __restrict__ out_w,
             int n) {
    __shared__ int sidx[TPB2 / 32][NS];

    const int w    = threadIdx.x >> 5;
    const int lane = threadIdx.x & 31;
    const int i    = blockIdx.x * (TPB2 / 32) + w;

    const uint4 mv = ((const uint4*)g_mask)[(size_t)i * SPLITS + lane];
    const int myc = __popc(mv.x) + __popc(mv.y) + __popc(mv.z) + __popc(mv.w);

    int incl = myc;
#pragma unroll
    for (int d = 1; d < 32; d <<= 1) {
        int v = __shfl_up_sync(FULL, incl, d);
        if (lane >= d) incl += v;
    }
    int total = __shfl_sync(FULL, incl, 31);
    if (total > NS) total = NS;
    int pos = incl - myc;

    const int pbase = lane * 128;
    unsigned ww;
    ww = mv.x; while (ww) { int t = __ffs(ww) - 1; if (pos < NS) sidx[w][pos] = pbase + t;       pos++; ww &= ww - 1; }
    ww = mv.y; while (ww) { int t = __ffs(ww) - 1; if (pos < NS) sidx[w][pos] = pbase + 32 + t;  pos++; ww &= ww - 1; }
    ww = mv.z; while (ww) { int t = __ffs(ww) - 1; if (pos < NS) sidx[w][pos] = pbase + 64 + t;  pos++; ww &= ww - 1; }
    ww = mv.w; while (ww) { int t = __ffs(ww) - 1; if (pos < NS) sidx[w][pos] = pbase + 96 + t;  pos++; ww &= ww - 1; }
    __syncwarp();

    const int idx  = sidx[w][lane < total ? lane : 0];
    const int rowg = (i / n) * n + idx;

    {
        const float4* fr = (const float4*)(pred + (size_t)rowg * CCH);
        float4 rr[5];
#pragma unroll
        for (int j = 0; j < 5; j++) rr[j] = fr[j];
        const float* ff = (const float*)rr;

        const float cv = (lane < CCH) ? pred[(size_t)i * CCH + lane] : 0.0f;
        float* o = out_pred + (size_t)i * (CCH * NS);
#pragma unroll
        for (int c = 0; c < CCH; c++)
            o[c * NS + lane] = ff[c] - __shfl_sync(FULL, cv, c);
    }

    {
        const int labk = g_labels[rowg];
        const int labi = g_labels[i];
        float* o = out_tgt + (size_t)i * (CCH * NS);
#pragma unroll
        for (int c = 0; c < CCH; c++) {
            const float a = (labk == c) ? 1.0f : 0.0f;
            const float b = (labi == c) ? 1.0f : 0.0f;
            o[c * NS + lane] = a - b;
        }
    }

    out_w[(size_t)i * NS + lane] = (lane < total) ? (1.0f / (float)total) : 0.0f;
}

// ---------------------------------------------------------------------------
// Launch. Inputs: xyz, xyz_batch_cnt, pred, tgt, new_xyz, new_xyz_batch_cnt.
// Output: concat(pred_local (m,C,NS), tgt_local (m,C,NS), weight (m,NS)) f32.
// All ops are graph-capturable (kernels + memset nodes; no allocs).
// ---------------------------------------------------------------------------
extern "C" void kernel_launch(void* const* d_in, const int* in_sizes, int n_in,
                              void* d_out, int out_size) {
    const float* xyz     = (const float*)d_in[0];
    const float* pred    = (const float*)d_in[2];
    const float* tgt     = (const float*)d_in[3];
    const float* new_xyz = (const float*)d_in[4];

    const int nb = in_sizes[1];          // 4
    const int N  = in_sizes[0] / 3;      // 16384
    const int n  = N / nb;               // 4096
    const int m  = in_sizes[4] / 3;      // 16384

    float* out_pred = (float*)d_out;
    float* out_tgt  = out_pred + (size_t)m * CCH * NS;
    float* out_w    = out_tgt  + (size_t)m * CCH * NS;

    void* mask_ptr = nullptr;
    void* cnt_ptr  = nullptr;
    cudaGetSymbolAddress(&mask_ptr, g_mask);
    cudaGetSymbolAddress(&cnt_ptr,  g_cellcnt);
    cudaMemsetAsync(mask_ptr, 0, (size_t)MAXM * 128 * sizeof(unsigned));
    cudaMemsetAsync(cnt_ptr,  0, NBATCH * CELLS * sizeof(int));

    bin_label_kernel<<<N / 256, 256>>>(xyz, tgt, n);
    scan_kernel<<<1, 1024>>>();
    scatter_kernel<<<N / 256, 256>>>(xyz, n);
    grid_query_kernel<<<m / 8, 256>>>(new_xyz, n, 4.0f);
    group_kernel<<<m / (TPB2 / 32), TPB2>>>(pred, out_pred, out_tgt, out_w, n);
}

// round 13
// speedup vs baseline: 1.9545x; 1.0909x over previous
#include <cuda_runtime.h>
#include <cstdint>

// Fixed dataset shape: B=4, n=4096/batch, C=20, NSAMPLE=32, R=2, cube 20.
#define NS      32
#define CCH     20
#define SPLITS  32           // mask layout: 32 uint4 per query (4096 bits)
#define TPB2    256
#define MAXM    16384
#define NBATCH  4
#define NPB     4096         // points per batch
#define GD      8            // grid cells per dim (cell size 2.5)
#define CELLS   512          // 8^3 per batch
#define FULL    0xFFFFFFFFu

// Scratch (device globals: allocation-free rule).
__device__ unsigned g_mask[(size_t)MAXM * 128];      // 4096-bit hit mask per query (8 MB)
__device__ int      g_labels[MAXM];
__device__ int      g_cellstart[NBATCH * CELLS];     // absolute start slot
__device__ int      g_cellend[NBATCH * CELLS];       // absolute end slot
__device__ float4   g_pts[MAXM];                     // {x, y, z, local_idx_as_float}

__device__ __forceinline__ int cell_of(float v) {
    int c = (int)(v * 0.4f);                         // / 2.5
    c = c < 0 ? 0 : (c > GD - 1 ? GD - 1 : c);
    return c;
}

// ---------------------------------------------------------------------------
// Kernel A: fused count + scan + scatter. One block per batch (1024 thr).
// Counting sort entirely in smem; writes cellstart/cellend + sorted points.
// ---------------------------------------------------------------------------
__global__ void __launch_bounds__(1024)
build_kernel(const float* __restrict__ xyz) {
    __shared__ int scnt[CELLS];
    __shared__ int sscan[CELLS];

    const int b = blockIdx.x;
    const int t = threadIdx.x;

    if (t < CELLS) scnt[t] = 0;
    __syncthreads();

    float px[4], py[4], pz[4];
    int   cid[4], rnk[4];
#pragma unroll
    for (int u = 0; u < 4; u++) {
        const int j = t + u * 1024;                  // local point index
        const float* p = xyz + ((size_t)b * NPB + j) * 3;
        px[u] = p[0]; py[u] = p[1]; pz[u] = p[2];
        cid[u] = (cell_of(px[u]) * GD + cell_of(py[u])) * GD + cell_of(pz[u]);
        rnk[u] = atomicAdd(&scnt[cid[u]], 1);
    }
    __syncthreads();

    // Hillis-Steele inclusive scan over 512 counts (threads 0..511 active).
    if (t < CELLS) sscan[t] = scnt[t];
    __syncthreads();
#pragma unroll
    for (int d = 1; d < CELLS; d <<= 1) {
        int v = 0;
        if (t < CELLS && t >= d) v = sscan[t - d];
        __syncthreads();
        if (t < CELLS) sscan[t] += v;
        __syncthreads();
    }
    if (t < CELLS) {
        const int excl = sscan[t] - scnt[t];
        g_cellstart[b * CELLS + t] = b * NPB + excl;
        g_cellend[b * CELLS + t]   = b * NPB + sscan[t];
        sscan[t] = excl;                             // reuse as exclusive base
    }
    __syncthreads();

#pragma unroll
    for (int u = 0; u < 4; u++) {
        const int j = t + u * 1024;
        const int slot = b * NPB + sscan[cid[u]] + rnk[u];
        g_pts[slot] = make_float4(px[u], py[u], pz[u], __int_as_float(j));
    }
}

// ---------------------------------------------------------------------------
// Kernel B: grid ball query, WARP per query, + folded label extraction.
// Per-axis ranges from cell_of(q +- 2.0001) (margin covers FP slop; the
// exact per-op-RN d2 test decides membership). Columns pruned by 2D min
// distance. Hits -> atomicOr into bitmask (order-independent; bit order ==
// index order => first-32 semantics exact).
// ---------------------------------------------------------------------------
__global__ void __launch_bounds__(256)
grid_query_kernel(const float* __restrict__ new_xyz,
                  const float* __restrict__ tgt,
                  int n, float r2) {
    const int w    = threadIdx.x >> 5;
    const int lane = threadIdx.x & 31;
    const int q    = blockIdx.x * 8 + w;
    const int b    = q / n;

    const float qx = new_xyz[3 * (size_t)q + 0];
    const float qy = new_xyz[3 * (size_t)q + 1];
    const float qz = new_xyz[3 * (size_t)q + 2];

    // Folded label extraction (one-hot row of this query).
    {
        const bool hot = (lane < CCH) && (tgt[(size_t)q * CCH + lane] > 0.5f);
        const unsigned bal = __ballot_sync(FULL, hot);
        if (lane == 0) g_labels[q] = __ffs(bal) - 1;
    }

    const int cx = cell_of(qx), cy = cell_of(qy);
    const int xlo = cell_of(qx - 2.0001f), xhi = cell_of(qx + 2.0001f);
    const int ylo = cell_of(qy - 2.0001f), yhi = cell_of(qy + 2.0001f);
    const int zlo = cell_of(qz - 2.0001f), zhi = cell_of(qz + 2.0001f);

    unsigned* mask = g_mask + (size_t)q * 128;

    for (int ix = xlo; ix <= xhi; ix++) {
        const float dxm = (ix < cx) ? (qx - (float)(ix + 1) * 2.5f)
                        : (ix > cx) ? ((float)ix * 2.5f - qx) : 0.0f;
        for (int iy = ylo; iy <= yhi; iy++) {
            const float dym = (iy < cy) ? (qy - (float)(iy + 1) * 2.5f)
                            : (iy > cy) ? ((float)iy * 2.5f - qy) : 0.0f;
            if (dxm * dxm + dym * dym > 4.01f) continue;   // column prune

            const int cbase = b * CELLS + (ix * GD + iy) * GD;
            const int st = g_cellstart[cbase + zlo];
            const int en = g_cellend[cbase + zhi];
            for (int k = st + lane; k < en; k += 32) {
                const float4 p = g_pts[k];
                const float dx = __fadd_rn(p.x, -qx);
                const float dy = __fadd_rn(p.y, -qy);
                const float dz = __fadd_rn(p.z, -qz);
                const float d2 = __fadd_rn(__fadd_rn(__fmul_rn(dx, dx),
                                                     __fmul_rn(dy, dy)),
                                           __fmul_rn(dz, dz));
                if (d2 < r2) {
                    const int j = __float_as_int(p.w);
                    atomicOr(&mask[j >> 5], 1u << (j & 31));
                }
            }
        }
    }
}

// ---------------------------------------------------------------------------
// Kernel C: warp-per-query group. Center features via UNIFORM broadcast
// loads (replaces 40 serialized SHFLs — MIO relief); rest as proven.
// ---------------------------------------------------------------------------
__global__ void __launch_bounds__(TPB2)
group_kernel(const float* __restrict__ pred,
             float* __restrict__ out_pred,
             float* __restrict__ out_tgt,
             float* __restrict__ out_w,
             int n) {
    __shared__ int sidx[TPB2 / 32][NS];

    const int w    = threadIdx.x >> 5;
    const int lane = threadIdx.x & 31;
    const int i    = blockIdx.x * (TPB2 / 32) + w;

    const uint4 mv = ((const uint4*)g_mask)[(size_t)i * SPLITS + lane];
    const int myc = __popc(mv.x) + __popc(mv.y) + __popc(mv.z) + __popc(mv.w);

    int incl = myc;
#pragma unroll
    for (int d = 1; d < 32; d <<= 1) {
        int v = __shfl_up_sync(FULL, incl, d);
        if (lane >= d) incl += v;
    }
    int total = __shfl_sync(FULL, incl, 31);
    if (total > NS) total = NS;
    int pos = incl - myc;

    const int pbase = lane * 128;
    unsigned ww;
    ww = mv.x; while (ww) { int t = __ffs(ww) - 1; if (pos < NS) sidx[w][pos] = pbase + t;       pos++; ww &= ww - 1; }
    ww = mv.y; while (ww) { int t = __ffs(ww) - 1; if (pos < NS) sidx[w][pos] = pbase + 32 + t;  pos++; ww &= ww - 1; }
    ww = mv.z; while (ww) { int t = __ffs(ww) - 1; if (pos < NS) sidx[w][pos] = pbase + 64 + t;  pos++; ww &= ww - 1; }
    ww = mv.w; while (ww) { int t = __ffs(ww) - 1; if (pos < NS) sidx[w][pos] = pbase + 96 + t;  pos++; ww &= ww - 1; }
    __syncwarp();

    const int idx  = sidx[w][lane < total ? lane : 0];
    const int rowg = (i / n) * n + idx;

    {
        const float4* fr = (const float4*)(pred + (size_t)rowg * CCH);
        float4 rr[5];
#pragma unroll
        for (int j = 0; j < 5; j++) rr[j] = fr[j];
        const float* ff = (const float*)rr;

        // Uniform (all-lanes-same-address) broadcast loads of the center row.
        const float4* cr = (const float4*)(pred + (size_t)i * CCH);
        float4 cc[5];
#pragma unroll
        for (int j = 0; j < 5; j++) cc[j] = cr[j];
        const float* cf = (const float*)cc;

        float* o = out_pred + (size_t)i * (CCH * NS);
#pragma unroll
        for (int c = 0; c < CCH; c++)
            o[c * NS + lane] = ff[c] - cf[c];
    }

    {
        const int labk = g_labels[rowg];
        const int labi = g_labels[i];
        float* o = out_tgt + (size_t)i * (CCH * NS);
#pragma unroll
        for (int c = 0; c < CCH; c++) {
            const float a = (labk == c) ? 1.0f : 0.0f;
            const float b2 = (labi == c) ? 1.0f : 0.0f;
            o[c * NS + lane] = a - b2;
        }
    }

    out_w[(size_t)i * NS + lane] = (lane < total) ? (1.0f / (float)total) : 0.0f;
}

// ---------------------------------------------------------------------------
// Launch. Inputs: xyz, xyz_batch_cnt, pred, tgt, new_xyz, new_xyz_batch_cnt.
// Output: concat(pred_local (m,C,NS), tgt_local (m,C,NS), weight (m,NS)) f32.
// 4 graph nodes total (1 memset + 3 kernels); all capturable, no allocs.
// ---------------------------------------------------------------------------
extern "C" void kernel_launch(void* const* d_in, const int* in_sizes, int n_in,
                              void* d_out, int out_size) {
    const float* xyz     = (const float*)d_in[0];
    const float* pred    = (const float*)d_in[2];
    const float* tgt     = (const float*)d_in[3];
    const float* new_xyz = (const float*)d_in[4];

    const int nb = in_sizes[1];          // 4
    const int N  = in_sizes[0] / 3;      // 16384
    const int n  = N / nb;               // 4096
    const int m  = in_sizes[4] / 3;      // 16384

    float* out_pred = (float*)d_out;
    float* out_tgt  = out_pred + (size_t)m * CCH * NS;
    float* out_w    = out_tgt  + (size_t)m * CCH * NS;

    void* mask_ptr = nullptr;
    cudaGetSymbolAddress(&mask_ptr, g_mask);
    cudaMemsetAsync(mask_ptr, 0, (size_t)MAXM * 128 * sizeof(unsigned));

    build_kernel<<<nb, 1024>>>(xyz);
    grid_query_kernel<<<m / 8, 256>>>(new_xyz, tgt, n, 4.0f);
    group_kernel<<<m / (TPB2 / 32), TPB2>>>(pred, out_pred, out_tgt, out_w, n);
}

// round 15
// speedup vs baseline: 2.1483x; 1.0991x over previous
#include <cuda_runtime.h>
#include <cstdint>

// Fixed dataset shape: B=4, n=4096/batch, C=20, NSAMPLE=32, R=2, cube 20.
#define NS      32
#define CCH     20
#define MAXM    16384
#define NBATCH  4
#define NPB     4096         // points per batch
#define GD      8            // grid cells per dim (cell size 2.5)
#define CELLS   512          // 8^3 per batch
#define FULL    0xFFFFFFFFu

// Scratch (device globals: allocation-free rule). ~320 KB total.
__device__ int    g_labels[MAXM];
__device__ int    g_cellstart[NBATCH * CELLS];   // absolute start slot
__device__ int    g_cellend[NBATCH * CELLS];     // absolute end slot
__device__ float4 g_pts[MAXM];                   // {x, y, z, local_idx_as_float}

__device__ __forceinline__ int cell_of(float v) {
    int c = (int)(v * 0.4f);                     // / 2.5
    c = c < 0 ? 0 : (c > GD - 1 ? GD - 1 : c);
    return c;
}

// ---------------------------------------------------------------------------
// Kernel A: fused count + scan + scatter + label extraction.
// One block per batch (1024 threads, 4 points each). Hierarchical shuffle
// scan (warp scans -> 16 warp sums -> warp-0 scan -> add back): 5 barriers.
// ---------------------------------------------------------------------------
__global__ void __launch_bounds__(1024)
build_kernel(const float* __restrict__ xyz, const float* __restrict__ tgt) {
    __shared__ int scnt[CELLS];
    __shared__ int sbase[CELLS];
    __shared__ int swsum[16];

    const int b = blockIdx.x;
    const int t = threadIdx.x;

    if (t < CELLS) scnt[t] = 0;
    __syncthreads();

    float px[4], py[4], pz[4];
    int   cid[4], rnk[4];
#pragma unroll
    for (int u = 0; u < 4; u++) {
        const int j = t + u * 1024;              // local point index
        const float* p = xyz + ((size_t)b * NPB + j) * 3;
        px[u] = p[0]; py[u] = p[1]; pz[u] = p[2];
        cid[u] = (cell_of(px[u]) * GD + cell_of(py[u])) * GD + cell_of(pz[u]);
        rnk[u] = atomicAdd(&scnt[cid[u]], 1);
    }

    // Label extraction (independent of the scan; overlaps atomics' latency).
#pragma unroll
    for (int u = 0; u < 4; u++) {
        const int row = b * NPB + t + u * 1024;
        const float4* r4 = (const float4*)(tgt + (size_t)row * CCH);
        int lab = 0;
#pragma unroll
        for (int j2 = 0; j2 < 5; j2++) {
            const float4 v = r4[j2];
            if (v.x > 0.5f) lab = 4 * j2 + 0;
            if (v.y > 0.5f) lab = 4 * j2 + 1;
            if (v.z > 0.5f) lab = 4 * j2 + 2;
            if (v.w > 0.5f) lab = 4 * j2 + 3;
        }
        g_labels[row] = lab;
    }
    __syncthreads();

    // Hierarchical scan over the 512 cell counts (threads 0..511).
    int incl = 0, myv = 0;
    if (t < CELLS) {
        myv  = scnt[t];
        incl = myv;
#pragma unroll
        for (int d = 1; d < 32; d <<= 1) {
            const int v = __shfl_up_sync(FULL, incl, d);
            if ((t & 31) >= d) incl += v;
        }
        if ((t & 31) == 31) swsum[t >> 5] = incl;
    }
    __syncthreads();
    if (t < 32) {
        int s = (t < 16) ? swsum[t] : 0;
#pragma unroll
        for (int d = 1; d < 16; d <<= 1) {
            const int v = __shfl_up_sync(FULL, s, d);
            if (t >= d) s += v;
        }
        if (t < 16) swsum[t] = s;                // inclusive warp sums
    }
    __syncthreads();
    if (t < CELLS) {
        const int wbase = (t >= 32) ? swsum[(t >> 5) - 1] : 0;
        const int excl  = wbase + incl - myv;
        g_cellstart[b * CELLS + t] = b * NPB + excl;
        g_cellend[b * CELLS + t]   = b * NPB + excl + myv;
        sbase[t] = excl;
    }
    __syncthreads();

#pragma unroll
    for (int u = 0; u < 4; u++) {
        const int j = t + u * 1024;
        const int slot = b * NPB + sbase[cid[u]] + rnk[u];
        g_pts[slot] = make_float4(px[u], py[u], pz[u], __int_as_float(j));
    }
}

// ---------------------------------------------------------------------------
// Kernel B: FUSED grid query + group. Warp per query.
//   Phase 1 (query): per-axis cell ranges from cell_of(q +- 2.0001), column
//     2D-min-distance prune, 32-lane strided coalesced candidate loads,
//     exact per-op-RN d2 test; hits -> atomicOr into a per-warp SMEM mask
//     (only this warp touches it; bit order == index order => first-32
//     semantics exact).
//   Phase 2 (group): popc/prefix/ffs extraction of the first 32 indices,
//     register gather of pred rows, uniform-broadcast center loads,
//     coalesced channel stores; tgt rebuilt from labels (one-hot algebra).
// No global mask, no memset, no separate group launch.
// ---------------------------------------------------------------------------
__global__ void __launch_bounds__(256)
fused_kernel(const float* __restrict__ new_xyz,
             const float* __restrict__ pred,
             float* __restrict__ out_pred,
             float* __restrict__ out_tgt,
             float* __restrict__ out_w,
             int n, float r2) {
    __shared__ unsigned smask[8][128];           // 512B mask per warp
    __shared__ int      sidx[8][NS];

    const int w    = threadIdx.x >> 5;
    const int lane = threadIdx.x & 31;
    const int q    = blockIdx.x * 8 + w;
    const int b    = q / n;

    // Zero this warp's mask (32 x uint4 = 128 words).
    ((uint4*)smask[w])[lane] = make_uint4(0, 0, 0, 0);
    __syncwarp();

    const float qx = new_xyz[3 * (size_t)q + 0];
    const float qy = new_xyz[3 * (size_t)q + 1];
    const float qz = new_xyz[3 * (size_t)q + 2];

    const int cx = cell_of(qx), cy = cell_of(qy);
    const int xlo = cell_of(qx - 2.0001f), xhi = cell_of(qx + 2.0001f);
    const int ylo = cell_of(qy - 2.0001f), yhi = cell_of(qy + 2.0001f);
    const int zlo = cell_of(qz - 2.0001f), zhi = cell_of(qz + 2.0001f);

    for (int ix = xlo; ix <= xhi; ix++) {
        const float dxm = (ix < cx) ? (qx - (float)(ix + 1) * 2.5f)
                        : (ix > cx) ? ((float)ix * 2.5f - qx) : 0.0f;
        for (int iy = ylo; iy <= yhi; iy++) {
            const float dym = (iy < cy) ? (qy - (float)(iy + 1) * 2.5f)
                            : (iy > cy) ? ((float)iy * 2.5f - qy) : 0.0f;
            if (dxm * dxm + dym * dym > 4.01f) continue;   // column prune

            const int cbase = b * CELLS + (ix * GD + iy) * GD;
            const int st = g_cellstart[cbase + zlo];
            const int en = g_cellend[cbase + zhi];
            for (int k = st + lane; k < en; k += 32) {
                const float4 p = g_pts[k];
                const float dx = __fadd_rn(p.x, -qx);
                const float dy = __fadd_rn(p.y, -qy);
                const float dz = __fadd_rn(p.z, -qz);
                const float d2 = __fadd_rn(__fadd_rn(__fmul_rn(dx, dx),
                                                     __fmul_rn(dy, dy)),
                                           __fmul_rn(dz, dz));
                if (d2 < r2) {
                    const int j = __float_as_int(p.w);
                    atomicOr(&smask[w][j >> 5], 1u << (j & 31));
                }
            }
        }
    }
    __syncwarp();

    // --- Phase 2: extract first-32 indices from the mask ---
    const uint4 mv = ((const uint4*)smask[w])[lane];
    const int myc = __popc(mv.x) + __popc(mv.y) + __popc(mv.z) + __popc(mv.w);

    int incl = myc;
#pragma unroll
    for (int d = 1; d < 32; d <<= 1) {
        const int v = __shfl_up_sync(FULL, incl, d);
        if (lane >= d) incl += v;
    }
    int total = __shfl_sync(FULL, incl, 31);
    if (total > NS) total = NS;
    int pos = incl - myc;

    const int pbase = lane * 128;
    unsigned ww;
    ww = mv.x; while (ww) { int t = __ffs(ww) - 1; if (pos < NS) sidx[w][pos] = pbase + t;       pos++; ww &= ww - 1; }
    ww = mv.y; while (ww) { int t = __ffs(ww) - 1; if (pos < NS) sidx[w][pos] = pbase + 32 + t;  pos++; ww &= ww - 1; }
    ww = mv.z; while (ww) { int t = __ffs(ww) - 1; if (pos < NS) sidx[w][pos] = pbase + 64 + t;  pos++; ww &= ww - 1; }
    ww = mv.w; while (ww) { int t = __ffs(ww) - 1; if (pos < NS) sidx[w][pos] = pbase + 96 + t;  pos++; ww &= ww - 1; }
    if (total == 0 && lane == 0) sidx[w][0] = q - b * n;   // defensive (self)
    __syncwarp();

    const int idx  = sidx[w][lane < total ? lane : 0];     // pad with first
    const int rowg = b * n + idx;

    // --- pred: register gather + uniform-broadcast center ---
    {
        const float4* fr = (const float4*)(pred + (size_t)rowg * CCH);
        float4 rr[5];
#pragma unroll
        for (int j = 0; j < 5; j++) rr[j] = fr[j];
        const float* ff = (const float*)rr;

        const float4* cr = (const float4*)(pred + (size_t)q * CCH);
        float4 cc[5];
#pragma unroll
        for (int j = 0; j < 5; j++) cc[j] = cr[j];
        const float* cf = (const float*)cc;

        float* o = out_pred + (size_t)q * (CCH * NS);
#pragma unroll
        for (int c = 0; c < CCH; c++)
            o[c * NS + lane] = ff[c] - cf[c];
    }

    // --- tgt: one-hot algebra from labels; values in {-1,0,1}, bit-exact ---
    {
        const int labk = g_labels[rowg];
        const int labi = g_labels[q];
        float* o = out_tgt + (size_t)q * (CCH * NS);
#pragma unroll
        for (int c = 0; c < CCH; c++) {
            const float a  = (labk == c) ? 1.0f : 0.0f;
            const float b2 = (labi == c) ? 1.0f : 0.0f;
            o[c * NS + lane] = a - b2;
        }
    }

    out_w[(size_t)q * NS + lane] = (lane < total) ? (1.0f / (float)total) : 0.0f;
}

// ---------------------------------------------------------------------------
// Launch. Inputs: xyz, xyz_batch_cnt, pred, tgt, new_xyz, new_xyz_batch_cnt.
// Output: concat(pred_local (m,C,NS), tgt_local (m,C,NS), weight (m,NS)) f32.
// TWO graph nodes; all capturable, no allocs.
// ---------------------------------------------------------------------------
extern "C" void kernel_launch(void* const* d_in, const int* in_sizes, int n_in,
                              void* d_out, int out_size) {
    const float* xyz     = (const float*)d_in[0];
    const float* pred    = (const float*)d_in[2];
    const float* tgt     = (const float*)d_in[3];
    const float* new_xyz = (const float*)d_in[4];

    const int nb = in_sizes[1];          // 4
    const int N  = in_sizes[0] / 3;      // 16384
    const int n  = N / nb;               // 4096
    const int m  = in_sizes[4] / 3;      // 16384

    float* out_pred = (float*)d_out;
    float* out_tgt  = out_pred + (size_t)m * CCH * NS;
    float* out_w    = out_tgt  + (size_t)m * CCH * NS;

    build_kernel<<<nb, 1024>>>(xyz, tgt);
    fused_kernel<<<m / 8, 256>>>(new_xyz, pred, out_pred, out_tgt, out_w, n, 4.0f);
}